// round 14
// baseline (speedup 1.0000x reference)
#include <cuda_runtime.h>
#include <cuda_fp16.h>
#include <cstdint>
#include <cstddef>

#define Bn 16
#define Tn 2048
#define Dn 1024
#define Hn 512
#define Mn (Bn*Tn)      // 32768
#define Nn 3072
#define Kn 1024

// scratch (static __device__ arrays: allocation-free)
__device__ __half g_Wt[(size_t)Nn * Kn];  // [n'][k], n' = plane*1024 + z*512 + h  (fp16)
__device__ __half g_xh[(size_t)Mn * Kn];  // x in fp16
__device__ __half g_Uh[(size_t)Mn * Nn];  // U in fp16: [m][n'], m = b*T + t

// ------------------------------- helpers -------------------------------
__device__ __forceinline__ uint32_t smem_u32(const void* p) {
    uint32_t a;
    asm("{ .reg .u64 t; cvta.to.shared.u64 t, %1; cvt.u32.u64 %0, t; }" : "=r"(a) : "l"(p));
    return a;
}

#define SWZ(o) ((o) ^ (((o) >> 3) & 0x70))

__device__ __forceinline__ void cp_async16(uint32_t saddr, const void* gptr) {
    asm volatile("cp.async.cg.shared.global [%0], [%1], 16;" :: "r"(saddr), "l"(gptr) : "memory");
}
__device__ __forceinline__ void cp_commit() {
    asm volatile("cp.async.commit_group;" ::: "memory");
}
template<int N> __device__ __forceinline__ void cp_wait() {
    asm volatile("cp.async.wait_group %0;" :: "n"(N) : "memory");
}

#define LDSM4(r, addr) \
    asm volatile("ldmatrix.sync.aligned.m8n8.x4.shared.b16 {%0,%1,%2,%3}, [%4];" \
        : "=r"((r)[0]), "=r"((r)[1]), "=r"((r)[2]), "=r"((r)[3]) : "r"(addr))

#define MMA_F16(d, a, b) \
    asm volatile("mma.sync.aligned.m16n8k16.row.col.f32.f16.f16.f32 " \
        "{%0,%1,%2,%3}, {%4,%5,%6,%7}, {%8,%9}, {%0,%1,%2,%3};" \
        : "+f"((d)[0]), "+f"((d)[1]), "+f"((d)[2]), "+f"((d)[3]) \
        : "r"((a)[0]), "r"((a)[1]), "r"((a)[2]), "r"((a)[3]), "r"((b)[0]), "r"((b)[1]))

// ------------------------- Kernel 0a: x -> fp16 -------------------------
__global__ void __launch_bounds__(256) sru_xh(const float* __restrict__ x) {
    size_t i = (size_t)blockIdx.x * 256 + threadIdx.x;
    float4 v = ((const float4*)x)[i];
    __half2* o = (__half2*)g_xh + i * 2;
    o[0] = __floats2half2_rn(v.x, v.y);
    o[1] = __floats2half2_rn(v.z, v.w);
}

// ------------------------- Kernel 0b: W repack (tiled transpose, fp16) -------------------------
__global__ void __launch_bounds__(256) sru_wt(const float* __restrict__ W) {
    __shared__ float tile[32][33];
    const int tx = threadIdx.x, ty = threadIdx.y;   // 32 x 8
    const int zh0 = blockIdx.x * 32;
    const int d0  = blockIdx.y * 32;
    const int kk  = blockIdx.z;
    #pragma unroll
    for (int r = 0; r < 4; r++) {
        int d = d0 + ty + r * 8;
        int zh = zh0 + tx;
        tile[ty + r * 8][tx] = W[(size_t)d * 3072 + zh * 3 + kk];
    }
    __syncthreads();
    #pragma unroll
    for (int r = 0; r < 4; r++) {
        int zh = zh0 + ty + r * 8;
        int d  = d0 + tx;
        g_Wt[(size_t)(kk * 1024 + zh) * 1024 + d] = __float2half_rn(tile[tx][ty + r * 8]);
    }
}

// ------------------------- Kernel 1: fp16 mma.sync GEMM, 128x128 tiles, 2 CTAs/SM, 1 barrier/chunk -------------------------
#define BM 128
#define BN 128
#define BK 64
#define NCHUNK (Kn / BK)            // 16
#define ASZ (BM * 128)              // 16384 bytes
#define BSZ (BN * 128)              // 16384 bytes
#define STGB (ASZ + BSZ)            // 32768
#define STAGES 3
#define SMEM_TOTAL (STAGES * STGB)  // 98304

__global__ void __launch_bounds__(256, 2) sru_gemm() {
    extern __shared__ __align__(1024) char smem[];
    const uint32_t sb = smem_u32(smem);
    const int tid = threadIdx.x;
    const int lane = tid & 31;
    const int w = tid >> 5;                 // 0..7
    const int m0 = blockIdx.y * BM;
    const int n0 = blockIdx.x * BN;
    const int wm = (w & 3) * 32;            // 4 m-warps
    const int wn = (w >> 2) * 64;           // 2 n-warps

    const int rr  = tid >> 3;   // 0..31
    const int seg = tid & 7;    // 0..7
    const __half* aS = g_xh + (size_t)(m0 + rr) * Kn + seg * 8;
    const __half* bS = g_Wt + (size_t)(n0 + rr) * Kn + seg * 8;
    uint32_t aO[4], bO[4];
    #pragma unroll
    for (int j = 0; j < 4; j++) {
        uint32_t o = (uint32_t)(rr + 32 * j) * 128 + seg * 16;
        aO[j] = SWZ(o);
        bO[j] = ASZ + SWZ(o);
    }

    auto ldchunk = [&](int c, int s) {
        uint32_t st = sb + (uint32_t)s * STGB;
        const __half* ap = aS + c * BK;
        const __half* bp = bS + c * BK;
        #pragma unroll
        for (int j = 0; j < 4; j++) cp_async16(st + aO[j], ap + (size_t)(32 * j) * Kn);
        #pragma unroll
        for (int j = 0; j < 4; j++) cp_async16(st + bO[j], bp + (size_t)(32 * j) * Kn);
        cp_commit();
    };

    uint32_t aRow[2], aXor[2];
    #pragma unroll
    for (int mi = 0; mi < 2; mi++) {
        uint32_t r = wm + mi * 16 + ((lane & 8) ? 8 : 0) + (lane & 7);
        aRow[mi] = r * 128; aXor[mi] = (r & 7) << 4;
    }
    const uint32_t aHi = (lane & 16) ? 16 : 0;
    uint32_t bRow[4], bXor[4];
    #pragma unroll
    for (int p = 0; p < 4; p++) {
        uint32_t r = wn + p * 16 + ((lane & 16) ? 8 : 0) + (lane & 7);
        bRow[p] = ASZ + r * 128; bXor[p] = (r & 7) << 4;
    }
    const uint32_t bHi = (lane & 8) ? 16 : 0;

    float acc[2][8][4];
    #pragma unroll
    for (int mi = 0; mi < 2; mi++)
        #pragma unroll
        for (int nj = 0; nj < 8; nj++)
            #pragma unroll
            for (int q = 0; q < 4; q++) acc[mi][nj][q] = 0.f;

    ldchunk(0, 0);
    ldchunk(1, 1);

    for (int i = 0; i < NCHUNK; i++) {
        if (i < NCHUNK - 1) cp_wait<1>();
        else                cp_wait<0>();
        __syncthreads();
        if (i + 2 < NCHUNK) ldchunk(i + 2, (i + 2) % 3);

        uint32_t st = sb + (uint32_t)(i % 3) * STGB;
        #pragma unroll
        for (int ks = 0; ks < 4; ks++) {
            uint32_t koff = ks * 32;
            uint32_t ar[2][4], br[4][4];
            #pragma unroll
            for (int mi = 0; mi < 2; mi++)
                LDSM4(ar[mi], st + aRow[mi] + ((koff + aHi) ^ aXor[mi]));
            #pragma unroll
            for (int p = 0; p < 4; p++)
                LDSM4(br[p], st + bRow[p] + ((koff + bHi) ^ bXor[p]));
            #pragma unroll
            for (int mi = 0; mi < 2; mi++)
                #pragma unroll
                for (int nj = 0; nj < 8; nj++)
                    MMA_F16(acc[mi][nj], ar[mi], &br[nj >> 1][(nj & 1) * 2]);
        }
    }

    // fp16 epilogue
    const int rowb = m0 + wm + (lane >> 2);
    const int colb = n0 + wn + (lane & 3) * 2;
    #pragma unroll
    for (int mi = 0; mi < 2; mi++)
        #pragma unroll
        for (int nj = 0; nj < 8; nj++) {
            size_t base = (size_t)(rowb + mi * 16) * Nn + colb + nj * 8;
            *(__half2*)(g_Uh + base) = __floats2half2_rn(acc[mi][nj][0], acc[mi][nj][1]);
            *(__half2*)(g_Uh + base + 8 * (size_t)Nn) = __floats2half2_rn(acc[mi][nj][2], acc[mi][nj][3]);
        }
}

// ------------------------- Kernel 2: SRU scan, 64 steps/tile, 4 ch/warp, 1 barrier/tile -------------------------
#define NT64 (Tn / 64)    // 32 tiles

__global__ void __launch_bounds__(512, 2) sru_scan(const float* __restrict__ bias,
                                                   float* __restrict__ out) {
    __shared__ __half sbuf[3][64][66];  // g,f,r tiles [t][ch], 33-word rows (odd -> bank-clean)
    __shared__ __half xbuf[64][66];

    const int tid = threadIdx.x;
    const int lane = tid & 31;
    const int w = tid >> 5;             // 0..15
    const int bx = blockIdx.x;          // 256 blocks: hg(8) z(2) b(16)
    const int hg = bx & 7;
    const int z  = (bx >> 3) & 1;
    const int b  = bx >> 4;
    const int h0 = hg * 64;
    const int fwd = (z == 0);
    const int c0 = 4 * w;

    float bf[4], br[4];
    #pragma unroll
    for (int c = 0; c < 4; c++) {
        bf[c] = bias[z * 1024 + h0 + c0 + c];
        br[c] = bias[z * 1024 + 512 + h0 + c0 + c];
    }

    const size_t bT = (size_t)b * Tn;
    const int tL = tid >> 3, sgL = tid & 7;     // loader role: row tL, 8-half seg sgL

    uint4 ru[3], rx;
    auto load_tile = [&](int it) {
        long t0 = fwd ? (long)it * 64 : (long)(NT64 - 1 - it) * 64;
        #pragma unroll
        for (int p = 0; p < 3; p++)
            ru[p] = *(const uint4*)(g_Uh + (bT + t0 + tL) * Nn + (size_t)p * 1024 + z * 512 + h0 + sgL * 8);
        rx = *(const uint4*)(g_xh + (bT + t0 + tL) * Kn + z * 512 + h0 + sgL * 8);
    };

    load_tile(0);
    float carry[4] = {0.f, 0.f, 0.f, 0.f};
    const int row0 = fwd ? 2 * lane     : 63 - 2 * lane;
    const int row1 = fwd ? 2 * lane + 1 : 62 - 2 * lane;
    // output pointers for this lane's two rows (direction already encoded in row0/row1)
    float* outc = out + z * 512 + h0 + c0;

    for (int it = 0; it < NT64; it++) {
        // stage regs -> smem; barrier also protects reuse (all reads of prev tile done)
        if (it) __syncthreads();
        #pragma unroll
        for (int p = 0; p < 3; p++) {
            uint32_t* d = (uint32_t*)&sbuf[p][tL][sgL * 8];
            d[0] = ru[p].x; d[1] = ru[p].y; d[2] = ru[p].z; d[3] = ru[p].w;
        }
        {
            uint32_t* d = (uint32_t*)&xbuf[tL][sgL * 8];
            d[0] = rx.x; d[1] = rx.y; d[2] = rx.z; d[3] = rx.w;
        }
        __syncthreads();
        if (it + 1 < NT64) load_tile(it + 1);   // prefetch overlaps compute

        // read 2 timesteps x 4 channels
        float2 Ga01 = __half22float2(*(const __half2*)&sbuf[0][row0][c0]);
        float2 Ga23 = __half22float2(*(const __half2*)&sbuf[0][row0][c0 + 2]);
        float2 Fa01 = __half22float2(*(const __half2*)&sbuf[1][row0][c0]);
        float2 Fa23 = __half22float2(*(const __half2*)&sbuf[1][row0][c0 + 2]);
        float2 Ra01 = __half22float2(*(const __half2*)&sbuf[2][row0][c0]);
        float2 Ra23 = __half22float2(*(const __half2*)&sbuf[2][row0][c0 + 2]);
        float2 Xa01 = __half22float2(*(const __half2*)&xbuf[row0][c0]);
        float2 Xa23 = __half22float2(*(const __half2*)&xbuf[row0][c0 + 2]);
        float2 Gb01 = __half22float2(*(const __half2*)&sbuf[0][row1][c0]);
        float2 Gb23 = __half22float2(*(const __half2*)&sbuf[0][row1][c0 + 2]);
        float2 Fb01 = __half22float2(*(const __half2*)&sbuf[1][row1][c0]);
        float2 Fb23 = __half22float2(*(const __half2*)&sbuf[1][row1][c0 + 2]);
        float2 Rb01 = __half22float2(*(const __half2*)&sbuf[2][row1][c0]);
        float2 Rb23 = __half22float2(*(const __half2*)&sbuf[2][row1][c0 + 2]);
        float2 Xb01 = __half22float2(*(const __half2*)&xbuf[row1][c0]);
        float2 Xb23 = __half22float2(*(const __half2*)&xbuf[row1][c0 + 2]);

        float Ga[4] = {Ga01.x, Ga01.y, Ga23.x, Ga23.y};
        float Fa[4] = {Fa01.x, Fa01.y, Fa23.x, Fa23.y};
        float Ra[4] = {Ra01.x, Ra01.y, Ra23.x, Ra23.y};
        float Xa[4] = {Xa01.x, Xa01.y, Xa23.x, Xa23.y};
        float Gb[4] = {Gb01.x, Gb01.y, Gb23.x, Gb23.y};
        float Fb[4] = {Fb01.x, Fb01.y, Fb23.x, Fb23.y};
        float Rb[4] = {Rb01.x, Rb01.y, Rb23.x, Rb23.y};
        float Xb[4] = {Xb01.x, Xb01.y, Xb23.x, Xb23.y};

        float aa[4], ab[4], ba[4], bb[4], A[4], Bv[4];
        #pragma unroll
        for (int c = 0; c < 4; c++) {
            aa[c] = __fdividef(1.f, 1.f + __expf(-(Fa[c] + bf[c])));
            ab[c] = __fdividef(1.f, 1.f + __expf(-(Fb[c] + bf[c])));
            ba[c] = (1.f - aa[c]) * Ga[c];
            bb[c] = (1.f - ab[c]) * Gb[c];
            A[c]  = ab[c] * aa[c];
            Bv[c] = fmaf(ab[c], ba[c], bb[c]);
        }

        // Kogge-Stone inclusive scan over pairs, 4 channels interleaved
        #pragma unroll
        for (int d = 1; d < 32; d <<= 1) {
            float Ap[4], Bp[4];
            #pragma unroll
            for (int c = 0; c < 4; c++) {
                Ap[c] = __shfl_up_sync(0xFFFFFFFFu, A[c], d);
                Bp[c] = __shfl_up_sync(0xFFFFFFFFu, Bv[c], d);
            }
            if (lane >= d) {
                #pragma unroll
                for (int c = 0; c < 4; c++) {
                    Bv[c] = fmaf(A[c], Bp[c], Bv[c]);
                    A[c] *= Ap[c];
                }
            }
        }

        float ca[4], cb[4];
        #pragma unroll
        for (int c = 0; c < 4; c++) {
            float Ae = __shfl_up_sync(0xFFFFFFFFu, A[c], 1);
            float Be = __shfl_up_sync(0xFFFFFFFFu, Bv[c], 1);
            if (lane == 0) { Ae = 1.f; Be = 0.f; }
            float cin = fmaf(Ae, carry[c], Be);
            ca[c] = fmaf(aa[c], cin, ba[c]);
            cb[c] = fmaf(ab[c], ca[c], bb[c]);
            float At = __shfl_sync(0xFFFFFFFFu, A[c], 31);
            float Bt = __shfl_sync(0xFFFFFFFFu, Bv[c], 31);
            carry[c] = fmaf(At, carry[c], Bt);
        }

        // direct 16B stores: lane writes its 4 contiguous fp32 channels for both rows
        {
            long t0 = fwd ? (long)it * 64 : (long)(NT64 - 1 - it) * 64;
            float4 v0, v1;
            {
                float rva = __fdividef(1.f, 1.f + __expf(-(Ra[0] + br[0])));
                float tha = 1.f - 2.f * __fdividef(1.f, 1.f + __expf(2.f * ca[0]));
                v0.x = fmaf(rva, tha - Xa[0], Xa[0]);
                float rvb = __fdividef(1.f, 1.f + __expf(-(Rb[0] + br[0])));
                float thb = 1.f - 2.f * __fdividef(1.f, 1.f + __expf(2.f * cb[0]));
                v1.x = fmaf(rvb, thb - Xb[0], Xb[0]);
            }
            {
                float rva = __fdividef(1.f, 1.f + __expf(-(Ra[1] + br[1])));
                float tha = 1.f - 2.f * __fdividef(1.f, 1.f + __expf(2.f * ca[1]));
                v0.y = fmaf(rva, tha - Xa[1], Xa[1]);
                float rvb = __fdividef(1.f, 1.f + __expf(-(Rb[1] + br[1])));
                float thb = 1.f - 2.f * __fdividef(1.f, 1.f + __expf(2.f * cb[1]));
                v1.y = fmaf(rvb, thb - Xb[1], Xb[1]);
            }
            {
                float rva = __fdividef(1.f, 1.f + __expf(-(Ra[2] + br[2])));
                float tha = 1.f - 2.f * __fdividef(1.f, 1.f + __expf(2.f * ca[2]));
                v0.z = fmaf(rva, tha - Xa[2], Xa[2]);
                float rvb = __fdividef(1.f, 1.f + __expf(-(Rb[2] + br[2])));
                float thb = 1.f - 2.f * __fdividef(1.f, 1.f + __expf(2.f * cb[2]));
                v1.z = fmaf(rvb, thb - Xb[2], Xb[2]);
            }
            {
                float rva = __fdividef(1.f, 1.f + __expf(-(Ra[3] + br[3])));
                float tha = 1.f - 2.f * __fdividef(1.f, 1.f + __expf(2.f * ca[3]));
                v0.w = fmaf(rva, tha - Xa[3], Xa[3]);
                float rvb = __fdividef(1.f, 1.f + __expf(-(Rb[3] + br[3])));
                float thb = 1.f - 2.f * __fdividef(1.f, 1.f + __expf(2.f * cb[3]));
                v1.w = fmaf(rvb, thb - Xb[3], Xb[3]);
            }
            *(float4*)(outc + (bT + t0 + row0) * Dn) = v0;
            *(float4*)(outc + (bT + t0 + row1) * Dn) = v1;
        }
    }

    // c_last: (B, 1, 2H) appended after out
    if (lane == 0) {
        float4 v = make_float4(carry[0], carry[1], carry[2], carry[3]);
        *(float4*)(out + (size_t)Bn * Tn * Dn + (size_t)b * 1024 + z * 512 + h0 + c0) = v;
    }
}

// ------------------------------- launch -------------------------------
extern "C" void kernel_launch(void* const* d_in, const int* in_sizes, int n_in,
                              void* d_out, int out_size) {
    const float* x    = (const float*)d_in[0];
    const float* W    = (const float*)d_in[1];
    const float* bias = (const float*)d_in[2];
    float* out = (float*)d_out;
    (void)in_sizes; (void)n_in; (void)out_size;

    cudaFuncSetAttribute(sru_gemm, cudaFuncAttributeMaxDynamicSharedMemorySize, SMEM_TOTAL);

    cudaStream_t s0 = 0;
    cudaStream_t sA;
    cudaStreamCreateWithFlags(&sA, cudaStreamNonBlocking);
    cudaEvent_t evFork, evW;
    cudaEventCreateWithFlags(&evFork, cudaEventDisableTiming);
    cudaEventCreateWithFlags(&evW,    cudaEventDisableTiming);

    // overlap W repack (side stream) with x->fp16 (main stream)
    cudaEventRecord(evFork, s0);
    cudaStreamWaitEvent(sA, evFork, 0);
    sru_wt<<<dim3(32, 32, 3), dim3(32, 8), 0, sA>>>(W);
    cudaEventRecord(evW, sA);

    sru_xh<<<(Mn * (Kn / 4)) / 256, 256, 0, s0>>>(x);
    cudaStreamWaitEvent(s0, evW, 0);

    sru_gemm<<<dim3(Nn / BN, Mn / BM), 256, SMEM_TOTAL, s0>>>();
    sru_scan<<<256, 512, 0, s0>>>(bias, out);

    cudaEventDestroy(evFork);
    cudaEventDestroy(evW);
    cudaStreamDestroy(sA);
}

// round 15
// speedup vs baseline: 1.0004x; 1.0004x over previous
#include <cuda_runtime.h>
#include <cuda_fp16.h>
#include <cstdint>
#include <cstddef>

#define Bn 16
#define Tn 2048
#define Dn 1024
#define Hn 512
#define Mn (Bn*Tn)      // 32768
#define Nn 3072
#define Kn 1024

// scratch (static __device__ arrays: allocation-free)
__device__ __half g_Wt[(size_t)Nn * Kn];  // [n'][k], n' = plane*1024 + z*512 + h  (fp16)
__device__ __half g_xh[(size_t)Mn * Kn];  // x in fp16, [m][zh]  (GEMM A)
__device__ __half g_xt[(size_t)Kn * Mn];  // x in fp16 TRANSPOSED [zh][m]  (scan residual)
__device__ __half g_Ut[(size_t)Nn * Mn];  // U fp16 TRANSPOSED [n'][m], m = b*T + t

// ------------------------------- helpers -------------------------------
__device__ __forceinline__ uint32_t smem_u32(const void* p) {
    uint32_t a;
    asm("{ .reg .u64 t; cvta.to.shared.u64 t, %1; cvt.u32.u64 %0, t; }" : "=r"(a) : "l"(p));
    return a;
}

#define SWZ(o) ((o) ^ (((o) >> 3) & 0x70))

__device__ __forceinline__ void cp_async16(uint32_t saddr, const void* gptr) {
    asm volatile("cp.async.cg.shared.global [%0], [%1], 16;" :: "r"(saddr), "l"(gptr) : "memory");
}
__device__ __forceinline__ void cp_commit() {
    asm volatile("cp.async.commit_group;" ::: "memory");
}
template<int N> __device__ __forceinline__ void cp_wait() {
    asm volatile("cp.async.wait_group %0;" :: "n"(N) : "memory");
}

#define LDSM4(r, addr) \
    asm volatile("ldmatrix.sync.aligned.m8n8.x4.shared.b16 {%0,%1,%2,%3}, [%4];" \
        : "=r"((r)[0]), "=r"((r)[1]), "=r"((r)[2]), "=r"((r)[3]) : "r"(addr))

#define MMA_F16(d, a, b) \
    asm volatile("mma.sync.aligned.m16n8k16.row.col.f32.f16.f16.f32 " \
        "{%0,%1,%2,%3}, {%4,%5,%6,%7}, {%8,%9}, {%0,%1,%2,%3};" \
        : "+f"((d)[0]), "+f"((d)[1]), "+f"((d)[2]), "+f"((d)[3]) \
        : "r"((a)[0]), "r"((a)[1]), "r"((a)[2]), "r"((a)[3]), "r"((b)[0]), "r"((b)[1]))

// ------------------------- Kernel 0a: x -> fp16 (copy + transpose) -------------------------
// blocks (Mn/32, 32), threads (32,8): tile 32(m) x 32(zh)
__global__ void __launch_bounds__(256) sru_xh(const float* __restrict__ x) {
    __shared__ __half tile[32][33];     // [zh][m]
    const int tx = threadIdx.x, ty = threadIdx.y;
    const int m0  = blockIdx.x * 32;
    const int zh0 = blockIdx.y * 32;
    #pragma unroll
    for (int r = 0; r < 4; r++) {
        int m = m0 + ty + r * 8;
        __half h = __float2half_rn(x[(size_t)m * Dn + zh0 + tx]);
        g_xh[(size_t)m * Dn + zh0 + tx] = h;
        tile[tx][ty + r * 8] = h;
    }
    __syncthreads();
    #pragma unroll
    for (int r = 0; r < 4; r++) {
        int zh = zh0 + ty + r * 8;
        g_xt[(size_t)zh * Mn + m0 + tx] = tile[ty + r * 8][tx];
    }
}

// ------------------------- Kernel 0b: W repack (tiled transpose, fp16) -------------------------
__global__ void __launch_bounds__(256) sru_wt(const float* __restrict__ W) {
    __shared__ float tile[32][33];
    const int tx = threadIdx.x, ty = threadIdx.y;   // 32 x 8
    const int zh0 = blockIdx.x * 32;
    const int d0  = blockIdx.y * 32;
    const int kk  = blockIdx.z;
    #pragma unroll
    for (int r = 0; r < 4; r++) {
        int d = d0 + ty + r * 8;
        int zh = zh0 + tx;
        tile[ty + r * 8][tx] = W[(size_t)d * 3072 + zh * 3 + kk];
    }
    __syncthreads();
    #pragma unroll
    for (int r = 0; r < 4; r++) {
        int zh = zh0 + ty + r * 8;
        int d  = d0 + tx;
        g_Wt[(size_t)(kk * 1024 + zh) * 1024 + d] = __float2half_rn(tile[tx][ty + r * 8]);
    }
}

// ------------------------- Kernel 1: fp16 mma.sync GEMM, transposed fp16 output -------------------------
#define BM 128
#define BN 128
#define BK 64
#define NCHUNK (Kn / BK)            // 16
#define ASZ (BM * 128)              // 16384 bytes
#define BSZ (BN * 128)              // 16384 bytes
#define STGB (ASZ + BSZ)            // 32768
#define STAGES 3
#define SMEM_TOTAL (STAGES * STGB)  // 98304
#define SR 136                      // epilogue transpose smem row stride (halfs)

__global__ void __launch_bounds__(256, 2) sru_gemm() {
    extern __shared__ __align__(1024) char smem[];
    const uint32_t sb = smem_u32(smem);
    const int tid = threadIdx.x;
    const int lane = tid & 31;
    const int w = tid >> 5;                 // 0..7
    const int m0 = blockIdx.y * BM;
    const int n0 = blockIdx.x * BN;
    const int wm = (w & 3) * 32;            // 4 m-warps
    const int wn = (w >> 2) * 64;           // 2 n-warps

    const int rr  = tid >> 3;   // 0..31
    const int seg = tid & 7;    // 0..7
    const __half* aS = g_xh + (size_t)(m0 + rr) * Kn + seg * 8;
    const __half* bS = g_Wt + (size_t)(n0 + rr) * Kn + seg * 8;
    uint32_t aO[4], bO[4];
    #pragma unroll
    for (int j = 0; j < 4; j++) {
        uint32_t o = (uint32_t)(rr + 32 * j) * 128 + seg * 16;
        aO[j] = SWZ(o);
        bO[j] = ASZ + SWZ(o);
    }

    auto ldchunk = [&](int c, int s) {
        uint32_t st = sb + (uint32_t)s * STGB;
        const __half* ap = aS + c * BK;
        const __half* bp = bS + c * BK;
        #pragma unroll
        for (int j = 0; j < 4; j++) cp_async16(st + aO[j], ap + (size_t)(32 * j) * Kn);
        #pragma unroll
        for (int j = 0; j < 4; j++) cp_async16(st + bO[j], bp + (size_t)(32 * j) * Kn);
        cp_commit();
    };

    uint32_t aRow[2], aXor[2];
    #pragma unroll
    for (int mi = 0; mi < 2; mi++) {
        uint32_t r = wm + mi * 16 + ((lane & 8) ? 8 : 0) + (lane & 7);
        aRow[mi] = r * 128; aXor[mi] = (r & 7) << 4;
    }
    const uint32_t aHi = (lane & 16) ? 16 : 0;
    uint32_t bRow[4], bXor[4];
    #pragma unroll
    for (int p = 0; p < 4; p++) {
        uint32_t r = wn + p * 16 + ((lane & 16) ? 8 : 0) + (lane & 7);
        bRow[p] = ASZ + r * 128; bXor[p] = (r & 7) << 4;
    }
    const uint32_t bHi = (lane & 8) ? 16 : 0;

    float acc[2][8][4];
    #pragma unroll
    for (int mi = 0; mi < 2; mi++)
        #pragma unroll
        for (int nj = 0; nj < 8; nj++)
            #pragma unroll
            for (int q = 0; q < 4; q++) acc[mi][nj][q] = 0.f;

    ldchunk(0, 0);
    ldchunk(1, 1);

    for (int i = 0; i < NCHUNK; i++) {
        if (i < NCHUNK - 1) cp_wait<1>();
        else                cp_wait<0>();
        __syncthreads();
        if (i + 2 < NCHUNK) ldchunk(i + 2, (i + 2) % 3);

        uint32_t st = sb + (uint32_t)(i % 3) * STGB;
        #pragma unroll
        for (int ks = 0; ks < 4; ks++) {
            uint32_t koff = ks * 32;
            uint32_t ar[2][4], br[4][4];
            #pragma unroll
            for (int mi = 0; mi < 2; mi++)
                LDSM4(ar[mi], st + aRow[mi] + ((koff + aHi) ^ aXor[mi]));
            #pragma unroll
            for (int p = 0; p < 4; p++)
                LDSM4(br[p], st + bRow[p] + ((koff + bHi) ^ bXor[p]));
            #pragma unroll
            for (int mi = 0; mi < 2; mi++)
                #pragma unroll
                for (int nj = 0; nj < 8; nj++)
                    MMA_F16(acc[mi][nj], ar[mi], &br[nj >> 1][(nj & 1) * 2]);
        }
    }

    // ---- epilogue: smem transpose -> g_Ut[n'][m], coalesced 16B stores along m ----
    __syncthreads();                        // mainloop smem reads done; reuse as eU
    __half* eU = (__half*)smem;             // [128 n][SR] halfs
    #pragma unroll
    for (int mi = 0; mi < 2; mi++)
        #pragma unroll
        for (int nj = 0; nj < 8; nj++) {
            int lr = wm + mi * 16 + (lane >> 2);
            int lc = wn + nj * 8 + (lane & 3) * 2;
            eU[lc * SR + lr]           = __float2half_rn(acc[mi][nj][0]);
            eU[(lc + 1) * SR + lr]     = __float2half_rn(acc[mi][nj][1]);
            eU[lc * SR + lr + 8]       = __float2half_rn(acc[mi][nj][2]);
            eU[(lc + 1) * SR + lr + 8] = __float2half_rn(acc[mi][nj][3]);
        }
    __syncthreads();
    #pragma unroll
    for (int jj = 0; jj < 8; jj++) {
        int g = jj * 256 + tid;
        int n = g >> 4, ms = g & 15;
        uint4 v = *(const uint4*)(eU + n * SR + ms * 8);
        *(uint4*)(g_Ut + (size_t)(n0 + n) * Mn + m0 + ms * 8) = v;
    }
}

// ------------------------- Kernel 2: SRU scan, time-major loads, 1 barrier/tile -------------------------
// 256 blocks x 512 threads; block = (b, z, 64 channels); warp w owns channels 4w..4w+3.
// Lane l covers scan positions 2l, 2l+1 of a 64-step tile; one LDG.32 per (plane,ch) yields both steps.
#define NT64 (Tn / 64)    // 32 tiles

__global__ void __launch_bounds__(512, 2) sru_scan(const float* __restrict__ bias,
                                                   float* __restrict__ out) {
    __shared__ float obuf[2][64][65];

    const int tid = threadIdx.x;
    const int lane = tid & 31;
    const int w = tid >> 5;             // 0..15
    const int bx = blockIdx.x;          // 256 blocks: hg(8) z(2) b(16)
    const int hg = bx & 7;
    const int z  = (bx >> 3) & 1;
    const int b  = bx >> 4;
    const int h0 = hg * 64;
    const int fwd = (z == 0);
    const int c0 = 4 * w;

    float bf[4], br[4];
    #pragma unroll
    for (int c = 0; c < 4; c++) {
        bf[c] = bias[z * 1024 + h0 + c0 + c];
        br[c] = bias[z * 1024 + 512 + h0 + c0 + c];
    }

    const size_t bT = (size_t)b * Tn;
    // word index into the [.][m] arrays for this lane's 4B (2 halfs)
    // forward: halfs (pos0,pos1) = times (2l, 2l+1) -> word at bT + it*64 + 2l
    // backward: pos0 = time 2047-it*64-2l (odd index tau), pos1 = tau-1; word at bT + tau-1
    const long wstep = fwd ? 64 : -64;
    long widx = fwd ? (long)bT + 2 * lane
                    : (long)bT + 2046 - 2 * lane;
    const size_t chBase = (size_t)(z * 512 + h0 + c0);

    uint32_t rg[4], rf[4], rr2[4], rx[4];
    auto load_tile = [&](long wi) {
        #pragma unroll
        for (int c = 0; c < 4; c++) {
            const __half* up = g_Ut + (chBase + c) * (size_t)Mn + wi;
            rg[c]  = *(const uint32_t*)(up);
            rf[c]  = *(const uint32_t*)(up + (size_t)1024 * Mn);
            rr2[c] = *(const uint32_t*)(up + (size_t)2048 * Mn);
            rx[c]  = *(const uint32_t*)(g_xt + (chBase + c) * (size_t)Mn + wi);
        }
    };

    load_tile(widx);
    float carry[4] = {0.f, 0.f, 0.f, 0.f};
    const int row0 = fwd ? 2 * lane     : 63 - 2 * lane;
    const int row1 = fwd ? 2 * lane + 1 : 62 - 2 * lane;

    for (int it = 0; it < NT64; it++) {
        // unpack: lo half = lower time index. pos0/pos1 mapping depends on direction.
        float Ga[4], Gb[4], aa[4], ab[4], Ra[4], Rb[4], Xa[4], Xb[4];
        #pragma unroll
        for (int c = 0; c < 4; c++) {
            float2 G = __half22float2(*(__half2*)&rg[c]);
            float2 F = __half22float2(*(__half2*)&rf[c]);
            float2 R = __half22float2(*(__half2*)&rr2[c]);
            float2 X = __half22float2(*(__half2*)&rx[c]);
            Ga[c] = fwd ? G.x : G.y;  Gb[c] = fwd ? G.y : G.x;
            aa[c] = fwd ? F.x : F.y;  ab[c] = fwd ? F.y : F.x;
            Ra[c] = fwd ? R.x : R.y;  Rb[c] = fwd ? R.y : R.x;
            Xa[c] = fwd ? X.x : X.y;  Xb[c] = fwd ? X.y : X.x;
        }

        float ba[4], bb[4], A[4], Bv[4];
        #pragma unroll
        for (int c = 0; c < 4; c++) {
            aa[c] = __fdividef(1.f, 1.f + __expf(-(aa[c] + bf[c])));
            ab[c] = __fdividef(1.f, 1.f + __expf(-(ab[c] + bf[c])));
            ba[c] = (1.f - aa[c]) * Ga[c];
            bb[c] = (1.f - ab[c]) * Gb[c];
            A[c]  = ab[c] * aa[c];
            Bv[c] = fmaf(ab[c], ba[c], bb[c]);
        }

        // Kogge-Stone inclusive scan over pairs, 4 channels interleaved
        #pragma unroll
        for (int d = 1; d < 32; d <<= 1) {
            float Ap[4], Bp[4];
            #pragma unroll
            for (int c = 0; c < 4; c++) {
                Ap[c] = __shfl_up_sync(0xFFFFFFFFu, A[c], d);
                Bp[c] = __shfl_up_sync(0xFFFFFFFFu, Bv[c], d);
            }
            if (lane >= d) {
                #pragma unroll
                for (int c = 0; c < 4; c++) {
                    Bv[c] = fmaf(A[c], Bp[c], Bv[c]);
                    A[c] *= Ap[c];
                }
            }
        }

        float ca[4], cb[4];
        #pragma unroll
        for (int c = 0; c < 4; c++) {
            float Ae = __shfl_up_sync(0xFFFFFFFFu, A[c], 1);
            float Be = __shfl_up_sync(0xFFFFFFFFu, Bv[c], 1);
            if (lane == 0) { Ae = 1.f; Be = 0.f; }
            float cin = fmaf(Ae, carry[c], Be);
            ca[c] = fmaf(aa[c], cin, ba[c]);
            cb[c] = fmaf(ab[c], ca[c], bb[c]);
            float At = __shfl_sync(0xFFFFFFFFu, A[c], 31);
            float Bt = __shfl_sync(0xFFFFFFFFu, Bv[c], 31);
            carry[c] = fmaf(At, carry[c], Bt);
        }

        // activation + stage into double-buffered obuf
        float* ob = &obuf[it & 1][0][0];
        #pragma unroll
        for (int c = 0; c < 4; c++) {
            float rva = __fdividef(1.f, 1.f + __expf(-(Ra[c] + br[c])));
            float rvb = __fdividef(1.f, 1.f + __expf(-(Rb[c] + br[c])));
            float tha = 1.f - 2.f * __fdividef(1.f, 1.f + __expf(2.f * ca[c]));
            float thb = 1.f - 2.f * __fdividef(1.f, 1.f + __expf(2.f * cb[c]));
            ob[row0 * 65 + c0 + c] = fmaf(rva, tha - Xa[c], Xa[c]);
            ob[row1 * 65 + c0 + c] = fmaf(rvb, thb - Xb[c], Xb[c]);
        }
        __syncthreads();

        // prefetch next tile while storing this one
        if (it + 1 < NT64) { widx += wstep; load_tile(widx); }

        // coalesced store: 1024 float4 over 512 threads (2 each)
        {
            long t0 = fwd ? (long)it * 64 : (long)(NT64 - 1 - it) * 64;
            #pragma unroll
            for (int j = 0; j < 2; j++) {
                int idx = tid + 512 * j;
                int t = idx >> 4, sg = idx & 15;
                const float* orow = &obuf[it & 1][t][sg * 4];
                float4 v = make_float4(orow[0], orow[1], orow[2], orow[3]);
                *(float4*)(out + (bT + t0 + t) * Dn + z * 512 + h0 + sg * 4) = v;
            }
        }
    }

    // c_last: (B, 1, 2H) appended after out
    if (lane == 0) {
        float4 v = make_float4(carry[0], carry[1], carry[2], carry[3]);
        *(float4*)(out + (size_t)Bn * Tn * Dn + (size_t)b * 1024 + z * 512 + h0 + c0) = v;
    }
}

// ------------------------------- launch -------------------------------
extern "C" void kernel_launch(void* const* d_in, const int* in_sizes, int n_in,
                              void* d_out, int out_size) {
    const float* x    = (const float*)d_in[0];
    const float* W    = (const float*)d_in[1];
    const float* bias = (const float*)d_in[2];
    float* out = (float*)d_out;
    (void)in_sizes; (void)n_in; (void)out_size;

    cudaFuncSetAttribute(sru_gemm, cudaFuncAttributeMaxDynamicSharedMemorySize, SMEM_TOTAL);

    sru_xh  <<<dim3(Mn / 32, Dn / 32), dim3(32, 8)>>>(x);
    sru_wt  <<<dim3(32, 32, 3), dim3(32, 8)>>>(W);
    sru_gemm<<<dim3(Nn / BN, Mn / BM), 256, SMEM_TOTAL>>>();
    sru_scan<<<256, 512>>>(bias, out);
}